// round 1
// baseline (speedup 1.0000x reference)
#include <cuda_runtime.h>

#define OBS   20
#define PRED  30
#define B_AG  32768
#define ROW2  65536       // B*2 (flat row size of (t, B, 2))
#define HD    64
#define ED    16
#define KD    80          // E + H
#define NG    256         // 4H
#define AB    64          // agents per block
#define NTHR  256
#define NBLK  (B_AG / AB) // 512
#define XH_STR 68         // padded stride for sXH [k][a]
#define HB_STR 72         // padded stride for hbuf [a][j]

// persistent LSTM state (device scratch; no runtime allocation)
__device__ float g_h[B_AG * HD];
__device__ float g_c[B_AG * HD];

// ---- packed fp32x2 helpers (Blackwell 2xFP32, PTX-only) ----
__device__ __forceinline__ unsigned long long dup2(float x) {
    unsigned long long r; unsigned u = __float_as_uint(x);
    asm("mov.b64 %0, {%1, %1};" : "=l"(r) : "r"(u));
    return r;
}
__device__ __forceinline__ void fma2(unsigned long long& d,
                                     unsigned long long a,
                                     unsigned long long b) {
    asm("fma.rn.f32x2 %0, %1, %2, %0;" : "+l"(d) : "l"(a), "l"(b));
}
__device__ __forceinline__ float2 unpk(unsigned long long v) {
    float lo, hi;
    asm("mov.b64 {%0, %1}, %2;" : "=f"(lo), "=f"(hi) : "l"(v));
    return make_float2(lo, hi);
}

// accurate-enough fast activations (ex2 + rcp paths)
__device__ __forceinline__ float sigm(float x) {
    float e = __expf(-x);
    return __fdividef(1.f, 1.f + e);
}
__device__ __forceinline__ float tanh_(float x) {
    float e = __expf(-2.f * x);
    return __fdividef(2.f, 1.f + e) - 1.f;
}

__global__ void __launch_bounds__(NTHR, 2)
lstm_step(int s, int first,
          const float* __restrict__ trajAbs,
          const float* __restrict__ decoderH,
          const float* __restrict__ W_ih, const float* __restrict__ W_hh,
          const float* __restrict__ b_ih, const float* __restrict__ b_hh,
          const float* __restrict__ embW, const float* __restrict__ embB,
          const float* __restrict__ h2pW, const float* __restrict__ h2pB,
          const float* __restrict__ ln1g, const float* __restrict__ ln1b,
          const float* __restrict__ ln2g, const float* __restrict__ ln2b,
          float* __restrict__ out)
{
    extern __shared__ float sm[];
    float* sW    = sm;              // 80*256   = 20480 floats (transposed [k][n])
    float* sXH   = sm + 20480;      // 80*68    = 5440  ([k][a], padded)
    float* sBias = sXH + 5440;      // 256      (b_ih + b_hh)
    float* sEmbW = sBias + 256;     // 16*40 = 640
    float* sSm   = sEmbW + 640;     // 352 small params
    float* sEmbB = sSm;             // 16
    float* sLn1g = sSm + 16;        // 40
    float* sLn1b = sSm + 56;        // 40
    float* sLn2g = sSm + 96;        // 64
    float* sLn2b = sSm + 160;       // 64
    float* sH2p  = sSm + 224;       // 128 (2x64)
    float* hbuf  = sW;              // alias: h tile [a][j] stride 72 (after GEMM)

    const int tid = threadIdx.x;
    const int b0  = blockIdx.x * AB;

    // ---------------- preload weights (transposed) ----------------
    {
        const int n = tid;  // 256 threads == 256 gate rows
        const float* wi = W_ih + n * ED;
#pragma unroll
        for (int k = 0; k < ED; k++) sW[k * NG + n] = wi[k];
        const float* wh = W_hh + n * HD;
#pragma unroll
        for (int k = 0; k < HD; k++) sW[(ED + k) * NG + n] = wh[k];
        sBias[n] = b_ih[n] + b_hh[n];
    }
    for (int i = tid; i < 640; i += NTHR) sEmbW[i] = embW[i];
    if (tid < 16) sEmbB[tid] = embB[tid];
    if (tid < 40) { sLn1g[tid] = ln1g[tid]; sLn1b[tid] = ln1b[tid]; }
    if (tid < 64) { sLn2g[tid] = ln2g[tid]; sLn2b[tid] = ln2b[tid]; }
    if (tid < 128) sH2p[tid] = h2pW[tid];
    __syncthreads();

    // ---------------- phase 1: gather + LN1 + embed + leaky_relu ----------------
    // agent a handled by 4 threads (jt = 0..3), each owns 10 of the 40 features.
    {
        const int a  = tid >> 2;
        const int jt = tid & 3;
        const int b  = b0 + a;
        const int fbase = b * 40 + jt * 10;
        float raw[10];
#pragma unroll
        for (int u = 0; u < 10; u++) {
            int f   = fbase + u;
            int t   = f >> 16;          // logical timestep (B*2 == 65536)
            int rem = f & 65535;
            int row = s + t;            // rolled buffer: traj_abs[s:] ++ pred[:s]
            raw[u] = (row < OBS) ? trajAbs[row * ROW2 + rem]
                                 : out[(row - OBS) * ROW2 + rem];
        }
        float sum = 0.f, sq = 0.f;
#pragma unroll
        for (int u = 0; u < 10; u++) { sum += raw[u]; sq += raw[u] * raw[u]; }
        sum += __shfl_xor_sync(0xffffffffu, sum, 1);
        sum += __shfl_xor_sync(0xffffffffu, sum, 2);
        sq  += __shfl_xor_sync(0xffffffffu, sq, 1);
        sq  += __shfl_xor_sync(0xffffffffu, sq, 2);
        const float mean = sum * 0.025f;
        const float var  = sq * 0.025f - mean * mean;
        const float rstd = rsqrtf(var + 1e-5f);

        float p[16];
#pragma unroll
        for (int e = 0; e < 16; e++) p[e] = 0.f;
#pragma unroll
        for (int u = 0; u < 10; u++) {
            int idx = jt * 10 + u;
            float xn = (raw[u] - mean) * rstd * sLn1g[idx] + sLn1b[idx];
#pragma unroll
            for (int e = 0; e < 16; e++) p[e] += xn * sEmbW[e * 40 + idx];
        }
#pragma unroll
        for (int e = 0; e < 16; e++) {
            p[e] += __shfl_xor_sync(0xffffffffu, p[e], 1);
            p[e] += __shfl_xor_sync(0xffffffffu, p[e], 2);
        }
#pragma unroll
        for (int i = 0; i < 4; i++) {
            int e = jt * 4 + i;
            float v = p[e] + sEmbB[e];
            v = v > 0.f ? v : 0.01f * v;   // leaky_relu(0.01)
            sXH[e * XH_STR + a] = v;
        }
    }
    // h tile load (coalesced read, padded-stride smem write)
    {
        const float* hs = first ? decoderH : g_h;
#pragma unroll
        for (int r = 0; r < 16; r++) {
            int idx = tid + r * NTHR;     // 0..4095
            int j = idx & 63;
            int a = idx >> 6;
            sXH[(ED + j) * XH_STR + a] = hs[(b0 + a) * HD + j];
        }
    }
    __syncthreads();

    // ---------------- phase 2: gates GEMM (f32x2 packed) ----------------
    // thread tile: 16 gates (j = 4*tx + q, all 4 gate types) x 4 agents (a = 4*ty + ai)
    const int tx = tid & 15;
    const int ty = tid >> 4;
    unsigned long long acc[4][2][4];
#pragma unroll
    for (int g = 0; g < 4; g++)
#pragma unroll
        for (int p = 0; p < 2; p++)
#pragma unroll
            for (int ai = 0; ai < 4; ai++) acc[g][p][ai] = 0ull;

    const float* xp = sXH + 4 * ty;
    const float* wp = sW + 4 * tx;
#pragma unroll 2
    for (int k = 0; k < KD; k++) {
        float4 xv = *(const float4*)(xp + k * XH_STR);
        unsigned long long xx[4];
        xx[0] = dup2(xv.x); xx[1] = dup2(xv.y);
        xx[2] = dup2(xv.z); xx[3] = dup2(xv.w);
#pragma unroll
        for (int g = 0; g < 4; g++) {
            ulonglong2 wv = *(const ulonglong2*)(wp + k * NG + 64 * g);
#pragma unroll
            for (int ai = 0; ai < 4; ai++) {
                fma2(acc[g][0][ai], wv.x, xx[ai]);
                fma2(acc[g][1][ai], wv.y, xx[ai]);
            }
        }
    }
    __syncthreads();   // all sW reads done before hbuf (alias) is written

    // ---------------- phase 3: LSTM cell ----------------
#pragma unroll
    for (int ai = 0; ai < 4; ai++) {
        const int b = b0 + 4 * ty + ai;
        float cold[4];
        if (first) { cold[0] = cold[1] = cold[2] = cold[3] = 0.f; }
        else {
            float4 cv = *(const float4*)(g_c + b * HD + 4 * tx);
            cold[0] = cv.x; cold[1] = cv.y; cold[2] = cv.z; cold[3] = cv.w;
        }
        float gate[4][4];
#pragma unroll
        for (int g = 0; g < 4; g++) {
            float2 u0 = unpk(acc[g][0][ai]);
            float2 u1 = unpk(acc[g][1][ai]);
            const float* bb = sBias + g * 64 + 4 * tx;
            gate[g][0] = u0.x + bb[0]; gate[g][1] = u0.y + bb[1];
            gate[g][2] = u1.x + bb[2]; gate[g][3] = u1.y + bb[3];
        }
        float4 cn, hn;
        float* cnp = &cn.x; float* hnp = &hn.x;
#pragma unroll
        for (int q = 0; q < 4; q++) {
            float ig = sigm(gate[0][q]);
            float fg = sigm(gate[1][q]);
            float gg = tanh_(gate[2][q]);
            float og = sigm(gate[3][q]);
            float c2 = fg * cold[q] + ig * gg;
            cnp[q] = c2;
            hnp[q] = og * tanh_(c2);
        }
        *(float4*)(g_c + b * HD + 4 * tx) = cn;
        *(float4*)(g_h + b * HD + 4 * tx) = hn;
        *(float4*)(hbuf + (4 * ty + ai) * HB_STR + 4 * tx) = hn;
    }
    __syncthreads();

    // ---------------- phase 4: LN2 + hidden2pos ----------------
    {
        const int a  = tid >> 2;
        const int jt = tid & 3;
        float hv[16];
        const float* hp = hbuf + a * HB_STR + jt * 16;
#pragma unroll
        for (int r = 0; r < 4; r++) {
            float4 v = *(const float4*)(hp + 4 * r);
            hv[4*r] = v.x; hv[4*r+1] = v.y; hv[4*r+2] = v.z; hv[4*r+3] = v.w;
        }
        float sum = 0.f, sq = 0.f;
#pragma unroll
        for (int u = 0; u < 16; u++) { sum += hv[u]; sq += hv[u] * hv[u]; }
        sum += __shfl_xor_sync(0xffffffffu, sum, 1);
        sum += __shfl_xor_sync(0xffffffffu, sum, 2);
        sq  += __shfl_xor_sync(0xffffffffu, sq, 1);
        sq  += __shfl_xor_sync(0xffffffffu, sq, 2);
        const float mean = sum * 0.015625f;
        const float var  = sq * 0.015625f - mean * mean;
        const float rstd = rsqrtf(var + 1e-5f);
        float p0 = 0.f, p1 = 0.f;
#pragma unroll
        for (int u = 0; u < 16; u++) {
            int j = jt * 16 + u;
            float xn = (hv[u] - mean) * rstd * sLn2g[j] + sLn2b[j];
            p0 += xn * sH2p[j];
            p1 += xn * sH2p[64 + j];
        }
        p0 += __shfl_xor_sync(0xffffffffu, p0, 1);
        p0 += __shfl_xor_sync(0xffffffffu, p0, 2);
        p1 += __shfl_xor_sync(0xffffffffu, p1, 1);
        p1 += __shfl_xor_sync(0xffffffffu, p1, 2);
        if (jt == 0) {
            float2 r = make_float2(p0 + h2pB[0], p1 + h2pB[1]);
            *(float2*)(out + s * ROW2 + (b0 + a) * 2) = r;
        }
    }
}

extern "C" void kernel_launch(void* const* d_in, const int* in_sizes, int n_in,
                              void* d_out, int out_size)
{
    const float* trajAbs  = (const float*)d_in[0];
    // d_in[1] = traj_rel (unused: use_rel_disp=False branch)
    const float* decoderH = (const float*)d_in[2];
    const float* W_ih = (const float*)d_in[3];
    const float* W_hh = (const float*)d_in[4];
    const float* b_ih = (const float*)d_in[5];
    const float* b_hh = (const float*)d_in[6];
    const float* embW = (const float*)d_in[7];
    const float* embB = (const float*)d_in[8];
    const float* h2pW = (const float*)d_in[9];
    const float* h2pB = (const float*)d_in[10];
    const float* ln1g = (const float*)d_in[11];
    const float* ln1b = (const float*)d_in[12];
    const float* ln2g = (const float*)d_in[13];
    const float* ln2b = (const float*)d_in[14];
    float* out = (float*)d_out;

    const int smemBytes = (20480 + 5440 + 256 + 640 + 352) * 4;  // 108672 B
    cudaFuncSetAttribute(lstm_step, cudaFuncAttributeMaxDynamicSharedMemorySize,
                         smemBytes);

    for (int s = 0; s < PRED; s++) {
        lstm_step<<<NBLK, NTHR, smemBytes>>>(
            s, (s == 0) ? 1 : 0, trajAbs, decoderH,
            W_ih, W_hh, b_ih, b_hh, embW, embB, h2pW, h2pB,
            ln1g, ln1b, ln2g, ln2b, out);
    }
}

// round 4
// speedup vs baseline: 2.0171x; 2.0171x over previous
#include <cuda_runtime.h>

#define OBS   20
#define PRED  30
#define B_AG  32768
#define ROW2  65536       // B*2 (flat row size of (t, B, 2))
#define HD    64
#define ED    16
#define KD    80          // E + H
#define NG    256         // 4H
#define AB    64          // agents per block
#define NTHR  256
#define NBLK  (B_AG / AB) // 512
#define XH_STR 68         // padded stride for sXH [k][a]
#define HB_STR 72         // padded stride for hbuf [a][j]

#define WROWS 84          // 80 W rows + 1 bias row + 3 pad (16B-chunk divisible)
#define WFLOATS (WROWS * NG)   // 21504 floats = 86016 B = 5376 x 16B chunks
#define SMALLN 1024

// persistent state + prepped params (device scratch; no runtime allocation)
__device__ __align__(16) float g_h[B_AG * HD];
__device__ __align__(16) float g_c[B_AG * HD];
__device__ __align__(16) float g_prep[WFLOATS];   // [k][n] transposed W, row 80 = b_ih+b_hh
__device__ __align__(16) float g_smalls[SMALLN];  // embW(640) embB(16) ln1g(40) ln1b(40) ln2g(64) ln2b(64) h2p(128) h2pb(2)

// ---- packed fp32x2 helpers (Blackwell 2xFP32, PTX-only) ----
__device__ __forceinline__ unsigned long long dup2(float x) {
    unsigned long long r; unsigned u = __float_as_uint(x);
    asm("mov.b64 %0, {%1, %1};" : "=l"(r) : "r"(u));
    return r;
}
__device__ __forceinline__ void fma2(unsigned long long& d,
                                     unsigned long long a,
                                     unsigned long long b) {
    asm("fma.rn.f32x2 %0, %1, %2, %0;" : "+l"(d) : "l"(a), "l"(b));
}
__device__ __forceinline__ float2 unpk(unsigned long long v) {
    float lo, hi;
    asm("mov.b64 {%0, %1}, %2;" : "=f"(lo), "=f"(hi) : "l"(v));
    return make_float2(lo, hi);
}
__device__ __forceinline__ void cp16(unsigned s, const void* g) {
    asm volatile("cp.async.cg.shared.global [%0], [%1], 16;" :: "r"(s), "l"(g));
}

// accurate-enough fast activations (ex2 + rcp paths)
__device__ __forceinline__ float sigm(float x) {
    float e = __expf(-x);
    return __fdividef(1.f, 1.f + e);
}
__device__ __forceinline__ float tanh_(float x) {
    float e = __expf(-2.f * x);
    return __fdividef(2.f, 1.f + e) - 1.f;
}

// ---------------- one-time prep: transpose W, pack smalls, init state ----------------
__global__ void prep_kernel(const float* __restrict__ decoderH,
                            const float* __restrict__ W_ih, const float* __restrict__ W_hh,
                            const float* __restrict__ b_ih, const float* __restrict__ b_hh,
                            const float* __restrict__ embW, const float* __restrict__ embB,
                            const float* __restrict__ ln1g, const float* __restrict__ ln1b,
                            const float* __restrict__ ln2g, const float* __restrict__ ln2b,
                            const float* __restrict__ h2pW, const float* __restrict__ h2pB)
{
    const int gid = blockIdx.x * blockDim.x + threadIdx.x;
    if (gid < WFLOATS) {
        const int k = gid >> 8;
        const int n = gid & 255;
        float v;
        if (k < ED)            v = W_ih[n * ED + k];
        else if (k < KD)       v = W_hh[n * HD + (k - ED)];
        else if (k == KD)      v = b_ih[n] + b_hh[n];
        else                   v = 0.f;
        g_prep[gid] = v;
    }
    if (gid < SMALLN) {
        float v;
        if (gid < 640)       v = embW[gid];
        else if (gid < 656)  v = embB[gid - 640];
        else if (gid < 696)  v = ln1g[gid - 656];
        else if (gid < 736)  v = ln1b[gid - 696];
        else if (gid < 800)  v = ln2g[gid - 736];
        else if (gid < 864)  v = ln2b[gid - 800];
        else if (gid < 992)  v = h2pW[gid - 864];
        else if (gid < 994)  v = h2pB[gid - 992];
        else                 v = 0.f;
        g_smalls[gid] = v;
    }
    if (gid < B_AG * HD) {
        g_h[gid] = decoderH[gid];
        g_c[gid] = 0.f;
    }
}

// ---------------- per-step fused kernel ----------------
__global__ void __launch_bounds__(NTHR, 2)
lstm_step(int s,
          const float* __restrict__ trajAbs,
          float* __restrict__ out)
{
    extern __shared__ float sm[];
    float* sW    = sm;                 // 84*256 = 21504 floats ([k][n], row 80 = bias)
    float* sXH   = sm + WFLOATS;       // 80*68  = 5440  ([k][a], padded)
    float* sSm   = sXH + 5440;         // 1024 small params
    float* sBias = sW + KD * NG;       // row 80
    float* sEmbW = sSm;                // 640
    float* sEmbB = sSm + 640;          // 16
    float* sLn1g = sSm + 656;          // 40
    float* sLn1b = sSm + 696;          // 40
    float* sLn2g = sSm + 736;          // 64
    float* sLn2b = sSm + 800;          // 64
    float* sH2p  = sSm + 864;          // 128
    float* hbuf  = sW;                 // alias: h tile [a][j] stride 72 (after GEMM)

    const int tid = threadIdx.x;
    const int b0  = blockIdx.x * AB;

    // kick async weight copy (overlaps with phase 1)
    {
        unsigned sw_addr = (unsigned)__cvta_generic_to_shared(sW);
#pragma unroll
        for (int i = 0; i < 21; i++) {
            int c = tid + i * NTHR;              // chunk of 16 B, 5376 total
            cp16(sw_addr + c * 16, (const char*)g_prep + c * 16);
        }
        asm volatile("cp.async.commit_group;");
    }
    // small params: 1 float4 per thread (1024 floats)
    ((float4*)sSm)[tid] = ((const float4*)g_smalls)[tid];
    __syncthreads();

    // ---------------- phase 1: gather + LN1 + embed + leaky_relu ----------------
    // agent a handled by 4 threads (jt = 0..3), each owns 10 of the 40 features.
    {
        const int a  = tid >> 2;
        const int jt = tid & 3;
        const int b  = b0 + a;
        const int fbase = b * 40 + jt * 10;
        float raw[10];
#pragma unroll
        for (int u = 0; u < 10; u++) {
            int f   = fbase + u;
            int t   = f >> 16;          // logical timestep (B*2 == 65536)
            int rem = f & 65535;
            int row = s + t;            // rolled buffer: traj_abs[s:] ++ pred[:s]
            raw[u] = (row < OBS) ? trajAbs[row * ROW2 + rem]
                                 : out[(row - OBS) * ROW2 + rem];
        }
        float sum = 0.f, sq = 0.f;
#pragma unroll
        for (int u = 0; u < 10; u++) { sum += raw[u]; sq += raw[u] * raw[u]; }
        sum += __shfl_xor_sync(0xffffffffu, sum, 1);
        sum += __shfl_xor_sync(0xffffffffu, sum, 2);
        sq  += __shfl_xor_sync(0xffffffffu, sq, 1);
        sq  += __shfl_xor_sync(0xffffffffu, sq, 2);
        const float mean = sum * 0.025f;
        const float var  = sq * 0.025f - mean * mean;
        const float rstd = rsqrtf(var + 1e-5f);

        float p[16];
#pragma unroll
        for (int e = 0; e < 16; e++) p[e] = 0.f;
#pragma unroll
        for (int u = 0; u < 10; u++) {
            int idx = jt * 10 + u;
            float xn = (raw[u] - mean) * rstd * sLn1g[idx] + sLn1b[idx];
#pragma unroll
            for (int e = 0; e < 16; e++) p[e] += xn * sEmbW[e * 40 + idx];
        }
#pragma unroll
        for (int e = 0; e < 16; e++) {
            p[e] += __shfl_xor_sync(0xffffffffu, p[e], 1);
            p[e] += __shfl_xor_sync(0xffffffffu, p[e], 2);
        }
#pragma unroll
        for (int i = 0; i < 4; i++) {
            int e = jt * 4 + i;
            float v = p[e] + sEmbB[e];
            v = v > 0.f ? v : 0.01f * v;   // leaky_relu(0.01)
            sXH[e * XH_STR + a] = v;
        }
    }
    // h tile load (coalesced read, padded-stride smem write)
    {
#pragma unroll
        for (int r = 0; r < 16; r++) {
            int idx = tid + r * NTHR;     // 0..4095
            int j = idx & 63;
            int a = idx >> 6;
            sXH[(ED + j) * XH_STR + a] = g_h[(b0 + a) * HD + j];
        }
    }
    asm volatile("cp.async.wait_group 0;");
    __syncthreads();

    // ---------------- phase 2: gates GEMM (f32x2 packed) ----------------
    // thread tile: 16 gates (j = 4*tx + q, all 4 gate types) x 4 agents (a = 4*ty + ai)
    const int tx = tid & 15;
    const int ty = tid >> 4;
    unsigned long long acc[4][2][4];
#pragma unroll
    for (int g = 0; g < 4; g++)
#pragma unroll
        for (int p = 0; p < 2; p++)
#pragma unroll
            for (int ai = 0; ai < 4; ai++) acc[g][p][ai] = 0ull;

    const float* xp = sXH + 4 * ty;
    const float* wp = sW + 4 * tx;
#pragma unroll 2
    for (int k = 0; k < KD; k++) {
        float4 xv = *(const float4*)(xp + k * XH_STR);
        unsigned long long xx[4];
        xx[0] = dup2(xv.x); xx[1] = dup2(xv.y);
        xx[2] = dup2(xv.z); xx[3] = dup2(xv.w);
#pragma unroll
        for (int g = 0; g < 4; g++) {
            ulonglong2 wv = *(const ulonglong2*)(wp + k * NG + 64 * g);
#pragma unroll
            for (int ai = 0; ai < 4; ai++) {
                fma2(acc[g][0][ai], wv.x, xx[ai]);
                fma2(acc[g][1][ai], wv.y, xx[ai]);
            }
        }
    }
    __syncthreads();   // all sW reads done before hbuf (alias) is written

    // ---------------- phase 3: LSTM cell ----------------
#pragma unroll
    for (int ai = 0; ai < 4; ai++) {
        const int b = b0 + 4 * ty + ai;
        float4 cv = *(const float4*)(g_c + b * HD + 4 * tx);
        float cold[4] = {cv.x, cv.y, cv.z, cv.w};
        float gate[4][4];
#pragma unroll
        for (int g = 0; g < 4; g++) {
            float2 u0 = unpk(acc[g][0][ai]);
            float2 u1 = unpk(acc[g][1][ai]);
            const float* bb = sBias + g * 64 + 4 * tx;
            gate[g][0] = u0.x + bb[0]; gate[g][1] = u0.y + bb[1];
            gate[g][2] = u1.x + bb[2]; gate[g][3] = u1.y + bb[3];
        }
        float4 cn, hn;
        float* cnp = &cn.x; float* hnp = &hn.x;
#pragma unroll
        for (int q = 0; q < 4; q++) {
            float ig = sigm(gate[0][q]);
            float fg = sigm(gate[1][q]);
            float gg = tanh_(gate[2][q]);
            float og = sigm(gate[3][q]);
            float c2 = fg * cold[q] + ig * gg;
            cnp[q] = c2;
            hnp[q] = og * tanh_(c2);
        }
        *(float4*)(g_c + b * HD + 4 * tx) = cn;
        *(float4*)(g_h + b * HD + 4 * tx) = hn;
        *(float4*)(hbuf + (4 * ty + ai) * HB_STR + 4 * tx) = hn;
    }
    __syncthreads();

    // ---------------- phase 4: LN2 + hidden2pos ----------------
    {
        const int a  = tid >> 2;
        const int jt = tid & 3;
        float hv[16];
        const float* hp = hbuf + a * HB_STR + jt * 16;
#pragma unroll
        for (int r = 0; r < 4; r++) {
            float4 v = *(const float4*)(hp + 4 * r);
            hv[4*r] = v.x; hv[4*r+1] = v.y; hv[4*r+2] = v.z; hv[4*r+3] = v.w;
        }
        float sum = 0.f, sq = 0.f;
#pragma unroll
        for (int u = 0; u < 16; u++) { sum += hv[u]; sq += hv[u] * hv[u]; }
        sum += __shfl_xor_sync(0xffffffffu, sum, 1);
        sum += __shfl_xor_sync(0xffffffffu, sum, 2);
        sq  += __shfl_xor_sync(0xffffffffu, sq, 1);
        sq  += __shfl_xor_sync(0xffffffffu, sq, 2);
        const float mean = sum * 0.015625f;
        const float var  = sq * 0.015625f - mean * mean;
        const float rstd = rsqrtf(var + 1e-5f);
        float p0 = 0.f, p1 = 0.f;
#pragma unroll
        for (int u = 0; u < 16; u++) {
            int j = jt * 16 + u;
            float xn = (hv[u] - mean) * rstd * sLn2g[j] + sLn2b[j];
            p0 += xn * sH2p[j];
            p1 += xn * sH2p[64 + j];
        }
        p0 += __shfl_xor_sync(0xffffffffu, p0, 1);
        p0 += __shfl_xor_sync(0xffffffffu, p0, 2);
        p1 += __shfl_xor_sync(0xffffffffu, p1, 1);
        p1 += __shfl_xor_sync(0xffffffffu, p1, 2);
        if (jt == 0) {
            float2 r = make_float2(p0 + sSm[992], p1 + sSm[993]);
            *(float2*)(out + s * ROW2 + (b0 + a) * 2) = r;
        }
    }
}

extern "C" void kernel_launch(void* const* d_in, const int* in_sizes, int n_in,
                              void* d_out, int out_size)
{
    const float* trajAbs  = (const float*)d_in[0];
    // d_in[1] = traj_rel (unused: use_rel_disp=False branch)
    const float* decoderH = (const float*)d_in[2];
    const float* W_ih = (const float*)d_in[3];
    const float* W_hh = (const float*)d_in[4];
    const float* b_ih = (const float*)d_in[5];
    const float* b_hh = (const float*)d_in[6];
    const float* embW = (const float*)d_in[7];
    const float* embB = (const float*)d_in[8];
    const float* h2pW = (const float*)d_in[9];
    const float* h2pB = (const float*)d_in[10];
    const float* ln1g = (const float*)d_in[11];
    const float* ln1b = (const float*)d_in[12];
    const float* ln2g = (const float*)d_in[13];
    const float* ln2b = (const float*)d_in[14];
    float* out = (float*)d_out;

    // NOTE: argument order matches prep_kernel's signature:
    // (decoderH, W_ih, W_hh, b_ih, b_hh, embW, embB, ln1g, ln1b, ln2g, ln2b, h2pW, h2pB)
    prep_kernel<<<(B_AG * HD + 255) / 256, 256>>>(
        decoderH, W_ih, W_hh, b_ih, b_hh, embW, embB,
        ln1g, ln1b, ln2g, ln2b, h2pW, h2pB);

    const int smemBytes = (WFLOATS + 5440 + SMALLN) * 4;  // 111872 B
    cudaFuncSetAttribute(lstm_step, cudaFuncAttributeMaxDynamicSharedMemorySize,
                         smemBytes);

    for (int s = 0; s < PRED; s++) {
        lstm_step<<<NBLK, NTHR, smemBytes>>>(s, trajAbs, out);
    }
}